// round 2
// baseline (speedup 1.0000x reference)
#include <cuda_runtime.h>
#include <math.h>

// CropAndResize: x [B,H,W,C=4] fp32, boxes [B,4] (y1,x1,y2,x2 in [0,1]),
// output [B,crop,crop,4] fp32 bilinear.
//
// 4 pixels per thread (stride blockDim) -> 16 independent corner gathers
// issued back-to-back per thread (MLP~16) to hide L2/DRAM latency.
// Stores remain fully warp-coalesced float4.

#define PIX_PER_THREAD 4

__global__ __launch_bounds__(256)
void crop_resize_kernel(const float* __restrict__ x,
                        const float* __restrict__ boxes,
                        float* __restrict__ out,
                        int H, int W, int crop) {
    const int b = blockIdx.y;
    const int npx = crop * crop;
    const int base = blockIdx.x * (blockDim.x * PIX_PER_THREAD) + threadIdx.x;

    // Box params (L1-resident broadcast)
    const float y1 = __ldg(&boxes[b * 4 + 0]);
    const float x1 = __ldg(&boxes[b * 4 + 1]);
    const float y2 = __ldg(&boxes[b * 4 + 2]);
    const float x2 = __ldg(&boxes[b * 4 + 3]);

    const float inv = 1.0f / (float)(crop - 1);
    const float hm1 = (float)(H - 1);
    const float wm1 = (float)(W - 1);
    const float dy = (y2 - y1) * hm1;
    const float dx = (x2 - x1) * wm1;
    const float oy = y1 * hm1;
    const float ox = x1 * wm1;

    const float4* __restrict__ xb = (const float4*)(x) + (size_t)b * H * W;
    float4* __restrict__ outb = (float4*)(out) + (size_t)b * npx;

    int  idx  [PIX_PER_THREAD];
    bool valid[PIX_PER_THREAD];
    float yl[PIX_PER_THREAD], xl[PIX_PER_THREAD];
    int off_tl[PIX_PER_THREAD], off_tr[PIX_PER_THREAD];
    int off_bl[PIX_PER_THREAD], off_br[PIX_PER_THREAD];

    #pragma unroll
    for (int k = 0; k < PIX_PER_THREAD; k++) {
        const int id = base + k * blockDim.x;
        idx[k] = id;
        const bool inb = (id < npx);
        const int row = inb ? (id / crop) : 0;
        const int col = inb ? (id - row * crop) : 0;

        const float gy = (float)row * inv;
        const float gx = (float)col * inv;
        const float in_y = oy + gy * dy;
        const float in_x = ox + gx * dx;

        valid[k] = inb && (in_y >= 0.0f) && (in_y <= hm1) &&
                          (in_x >= 0.0f) && (in_x <= wm1);

        const float top_f  = floorf(in_y);
        const float left_f = floorf(in_x);
        yl[k] = in_y - top_f;
        xl[k] = in_x - left_f;

        int t = min(max((int)top_f, 0), H - 1);
        int bo = min(t + 1, H - 1);
        int l = min(max((int)left_f, 0), W - 1);
        int r = min(l + 1, W - 1);

        off_tl[k] = t * W + l;
        off_tr[k] = t * W + r;
        off_bl[k] = bo * W + l;
        off_br[k] = bo * W + r;
    }

    // Issue all 16 gathers before any consumption (max MLP).
    float4 tl[PIX_PER_THREAD], tr[PIX_PER_THREAD];
    float4 bl[PIX_PER_THREAD], br[PIX_PER_THREAD];
    #pragma unroll
    for (int k = 0; k < PIX_PER_THREAD; k++) {
        const int o_tl = valid[k] ? off_tl[k] : 0;
        const int o_tr = valid[k] ? off_tr[k] : 0;
        const int o_bl = valid[k] ? off_bl[k] : 0;
        const int o_br = valid[k] ? off_br[k] : 0;
        tl[k] = __ldg(xb + o_tl);
        tr[k] = __ldg(xb + o_tr);
        bl[k] = __ldg(xb + o_bl);
        br[k] = __ldg(xb + o_br);
    }

    #pragma unroll
    for (int k = 0; k < PIX_PER_THREAD; k++) {
        if (idx[k] >= npx) continue;
        float4 res = make_float4(0.f, 0.f, 0.f, 0.f);
        if (valid[k]) {
            const float xk = xl[k], yk = yl[k];
            float tx0 = tl[k].x + (tr[k].x - tl[k].x) * xk;
            float ty0 = tl[k].y + (tr[k].y - tl[k].y) * xk;
            float tz0 = tl[k].z + (tr[k].z - tl[k].z) * xk;
            float tw0 = tl[k].w + (tr[k].w - tl[k].w) * xk;
            float bx0 = bl[k].x + (br[k].x - bl[k].x) * xk;
            float by0 = bl[k].y + (br[k].y - bl[k].y) * xk;
            float bz0 = bl[k].z + (br[k].z - bl[k].z) * xk;
            float bw0 = bl[k].w + (br[k].w - bl[k].w) * xk;
            res.x = tx0 + (bx0 - tx0) * yk;
            res.y = ty0 + (by0 - ty0) * yk;
            res.z = tz0 + (bz0 - tz0) * yk;
            res.w = tw0 + (bw0 - tw0) * yk;
        }
        outb[idx[k]] = res;
    }
}

extern "C" void kernel_launch(void* const* d_in, const int* in_sizes, int n_in,
                              void* d_out, int out_size) {
    const float* x     = (const float*)d_in[0];
    const float* boxes = (const float*)d_in[1];
    float* out = (float*)d_out;

    const int B = in_sizes[1] / 4;          // boxes is [B,4]
    const int C = 4;
    const long long hw = (long long)in_sizes[0] / ((long long)B * C);
    int H = (int)(sqrt((double)hw) + 0.5);
    int W = H;
    const long long cc = (long long)out_size / ((long long)B * C);
    int crop = (int)(sqrt((double)cc) + 0.5);

    const int npx = crop * crop;
    const int threads = 256;
    const int pix_per_block = threads * PIX_PER_THREAD;
    dim3 grid((npx + pix_per_block - 1) / pix_per_block, B);
    crop_resize_kernel<<<grid, threads>>>(x, boxes, out, H, W, crop);
}

// round 3
// speedup vs baseline: 1.2937x; 1.2937x over previous
#include <cuda_runtime.h>
#include <math.h>

// CropAndResize: x [B,H,W,C=4] fp32, boxes [B,4] (y1,x1,y2,x2 in [0,1]),
// output [B,crop,crop,4] fp32 bilinear.
//
// 2 pixels per thread (stride blockDim), compact corner addressing
// (base + dRight + dBelow) to keep regs <= 64 -> 50% occupancy with
// MLP=8 independent gathers per thread.

#define PPT 2

__global__ __launch_bounds__(256, 4)
void crop_resize_kernel(const float* __restrict__ x,
                        const float* __restrict__ boxes,
                        float* __restrict__ out,
                        int H, int W, int crop) {
    const int b = blockIdx.y;
    const int npx = crop * crop;
    const int base_id = blockIdx.x * (blockDim.x * PPT) + threadIdx.x;

    const float y1 = __ldg(&boxes[b * 4 + 0]);
    const float x1 = __ldg(&boxes[b * 4 + 1]);
    const float y2 = __ldg(&boxes[b * 4 + 2]);
    const float x2 = __ldg(&boxes[b * 4 + 3]);

    const float inv = 1.0f / (float)(crop - 1);
    const float hm1 = (float)(H - 1);
    const float wm1 = (float)(W - 1);
    const float dy = (y2 - y1) * hm1;
    const float dx = (x2 - x1) * wm1;
    const float oy = y1 * hm1;
    const float ox = x1 * wm1;

    const float4* __restrict__ xb = (const float4*)(x) + (size_t)b * H * W;
    float4* __restrict__ outb = (float4*)(out) + (size_t)b * npx;

    int   cbase[PPT];   // t*W + l  (0 when invalid)
    int   dR[PPT];      // r - l     in {0,1}
    int   dBW[PPT];     // (bo-t)*W  in {0,W}
    float yl[PPT], xl[PPT];
    bool  valid[PPT];

    #pragma unroll
    for (int k = 0; k < PPT; k++) {
        const int id = base_id + k * blockDim.x;
        const bool inb = (id < npx);
        const int row = inb ? (id / crop) : 0;
        const int col = inb ? (id - row * crop) : 0;

        const float in_y = fmaf((float)row * inv, dy, oy);
        const float in_x = fmaf((float)col * inv, dx, ox);

        valid[k] = inb && (in_y >= 0.0f) && (in_y <= hm1) &&
                          (in_x >= 0.0f) && (in_x <= wm1);

        const float top_f  = floorf(in_y);
        const float left_f = floorf(in_x);
        yl[k] = in_y - top_f;
        xl[k] = in_x - left_f;

        int t = min(max((int)top_f, 0), H - 1);
        int l = min(max((int)left_f, 0), W - 1);
        dR[k]  = (l < W - 1) ? 1 : 0;
        dBW[k] = (t < H - 1) ? W : 0;
        cbase[k] = valid[k] ? (t * W + l) : 0;
    }

    // Batch all gathers (MLP = 4*PPT)
    float4 tl[PPT], tr[PPT], bl[PPT], br[PPT];
    #pragma unroll
    for (int k = 0; k < PPT; k++) {
        const int o = cbase[k];
        tl[k] = __ldg(xb + o);
        tr[k] = __ldg(xb + o + dR[k]);
        bl[k] = __ldg(xb + o + dBW[k]);
        br[k] = __ldg(xb + o + dBW[k] + dR[k]);
    }

    #pragma unroll
    for (int k = 0; k < PPT; k++) {
        const int id = base_id + k * blockDim.x;
        if (id >= npx) continue;
        float4 res = make_float4(0.f, 0.f, 0.f, 0.f);
        if (valid[k]) {
            const float xk = xl[k], yk = yl[k];
            const float tx0 = fmaf(tr[k].x - tl[k].x, xk, tl[k].x);
            const float ty0 = fmaf(tr[k].y - tl[k].y, xk, tl[k].y);
            const float tz0 = fmaf(tr[k].z - tl[k].z, xk, tl[k].z);
            const float tw0 = fmaf(tr[k].w - tl[k].w, xk, tl[k].w);
            const float bx0 = fmaf(br[k].x - bl[k].x, xk, bl[k].x);
            const float by0 = fmaf(br[k].y - bl[k].y, xk, bl[k].y);
            const float bz0 = fmaf(br[k].z - bl[k].z, xk, bl[k].z);
            const float bw0 = fmaf(br[k].w - bl[k].w, xk, bl[k].w);
            res.x = fmaf(bx0 - tx0, yk, tx0);
            res.y = fmaf(by0 - ty0, yk, ty0);
            res.z = fmaf(bz0 - tz0, yk, tz0);
            res.w = fmaf(bw0 - tw0, yk, tw0);
        }
        outb[id] = res;
    }
}

extern "C" void kernel_launch(void* const* d_in, const int* in_sizes, int n_in,
                              void* d_out, int out_size) {
    const float* x     = (const float*)d_in[0];
    const float* boxes = (const float*)d_in[1];
    float* out = (float*)d_out;

    const int B = in_sizes[1] / 4;          // boxes is [B,4]
    const int C = 4;
    const long long hw = (long long)in_sizes[0] / ((long long)B * C);
    int H = (int)(sqrt((double)hw) + 0.5);
    int W = H;
    const long long cc = (long long)out_size / ((long long)B * C);
    int crop = (int)(sqrt((double)cc) + 0.5);

    const int npx = crop * crop;
    const int threads = 256;
    const int pix_per_block = threads * PPT;
    dim3 grid((npx + pix_per_block - 1) / pix_per_block, B);
    crop_resize_kernel<<<grid, threads>>>(x, boxes, out, H, W, crop);
}